// round 3
// baseline (speedup 1.0000x reference)
#include <cuda_runtime.h>

// reshape_78271484002964: [16,64,256,256] f32, SPLIT=(2,16,16), map_type=1.
// out[b,i,j,k,cc,hh,ww] = in[b,i,cc,j,hh,k,ww]
// with sizes b=16, i=2, j=16, k=16, cc=32, hh=16, ww=16.
//
// Work in float4 units (ww -> 4 x float4, ww4 in [0,4)).
// Output float4 linear index g bit layout (fast->slow):
//   ww4: bits [0,2)   hh: [2,6)   cc: [6,11)   k: [11,15)
//   j:   [15,19)      i: bit 19   b: [20,24)
// Input float4 strides: ww4=1, k=1<<2, hh=1<<6, j=1<<10, cc=1<<14,
//   i=1<<19, b=1<<20  (bits >= 19 are identical in both layouts).

__global__ void __launch_bounds__(256)
reshape_78271484002964_kernel(const float4* __restrict__ in,
                              float4* __restrict__ out) {
    unsigned g = blockIdx.x * 256u + threadIdx.x;

    unsigned in4 =  (g & 3u)                      // ww4
                 | (((g >> 11) & 15u) << 2)       // k
                 | (((g >> 2)  & 15u) << 6)       // hh
                 | (((g >> 15) & 15u) << 10)      // j
                 | (((g >> 6)  & 31u) << 14)      // cc
                 |  (g & 0xFFF80000u);            // i, b pass through

    out[g] = in[in4];
}

extern "C" void kernel_launch(void* const* d_in, const int* in_sizes, int n_in,
                              void* d_out, int out_size) {
    const float4* in  = (const float4*)d_in[0];
    float4*       out = (float4*)d_out;
    // 16*64*256*256 floats = 67,108,864 -> 16,777,216 float4
    const unsigned n4 = 16u * 64u * 256u * 256u / 4u;
    reshape_78271484002964_kernel<<<n4 / 256u, 256u>>>(in, out);
}

// round 4
// speedup vs baseline: 1.1219x; 1.1219x over previous
#include <cuda_runtime.h>

// reshape_78271484002964: [16,64,256,256] f32, SPLIT=(2,16,16), map_type=1.
// out[b,i,j,k,cc,hh,ww] = in[b,i,cc,j,hh,k,ww]
// sizes: b=16, i=2, j=16, k=16, cc=32, hh=16, ww=16.
//
// float4-unit bit map. Output float4 index g (fast->slow):
//   ww4: bits [0,2)  hh: [2,6)  cc: [6,11)  k: [11,15)
//   j: [15,19)  i: bit 19  b: [20,24)
// Input float4 strides: ww4=1, k=1<<2, hh=1<<6, j=1<<10, cc=1<<14,
//   bits >= 19 (i,b) pass through unchanged.
//
// R4: 4 float4 per thread (stride 256 inside a 1024-wide block tile) for
// MLP=4 on the load side; streaming loads/stores (.cs) since data is
// single-touch.

__device__ __forceinline__ unsigned out_to_in(unsigned g) {
    return  (g & 3u)                      // ww4
         | (((g >> 11) & 15u) << 2)       // k
         | (((g >> 2)  & 15u) << 6)       // hh
         | (((g >> 15) & 15u) << 10)      // j
         | (((g >> 6)  & 31u) << 14)      // cc
         |  (g & 0xFFF80000u);            // i, b pass through
}

__global__ void __launch_bounds__(256)
reshape_78271484002964_kernel(const float4* __restrict__ in,
                              float4* __restrict__ out) {
    unsigned g0 = blockIdx.x * 1024u + threadIdx.x;

    // 4 independent loads first (MLP=4), then 4 stores.
    float4 v0 = __ldcs(in + out_to_in(g0));
    float4 v1 = __ldcs(in + out_to_in(g0 + 256u));
    float4 v2 = __ldcs(in + out_to_in(g0 + 512u));
    float4 v3 = __ldcs(in + out_to_in(g0 + 768u));

    __stcs(out + g0,        v0);
    __stcs(out + g0 + 256u, v1);
    __stcs(out + g0 + 512u, v2);
    __stcs(out + g0 + 768u, v3);
}

extern "C" void kernel_launch(void* const* d_in, const int* in_sizes, int n_in,
                              void* d_out, int out_size) {
    const float4* in  = (const float4*)d_in[0];
    float4*       out = (float4*)d_out;
    // 67,108,864 floats -> 16,777,216 float4 -> 16384 blocks x 256 thr x 4 f4
    reshape_78271484002964_kernel<<<16384, 256>>>(in, out);
}